// round 14
// baseline (speedup 1.0000x reference)
#include <cuda_runtime.h>
#include <cuda_bf16.h>
#include <stdint.h>
#include <math.h>

typedef __nv_bfloat16  bf16;
typedef __nv_bfloat162 bf162;

#define T_SEQ 4096

// ---------------------------------------------------------------------------
// Scratch (device globals; no allocation allowed)
// ---------------------------------------------------------------------------
// int8 limb arrays: one u32 = 4 consecutive-k int8. Row = 256 u32 (K=1024).
__device__ __align__(16) uint32_t g_xi1[T_SEQ * 256],  g_xi2[T_SEQ * 256];
__device__ __align__(16) uint32_t g_wqi1[3072 * 256],  g_wqi2[3072 * 256];
__device__ __align__(16) uint32_t g_wpi1[1024 * 256],  g_wpi2[1024 * 256];
__device__ __align__(16) uint32_t g_yi1[T_SEQ * 256],  g_yi2[T_SEQ * 256];
__device__ float g_sx[T_SEQ], g_swq[3072], g_swp[1024], g_sy[T_SEQ];
// bf16 split tensors for the attention kernel (unchanged interface)
__device__ __align__(16) bf162 g_qh[T_SEQ * 1536], g_ql[T_SEQ * 1536];
__device__ __align__(16) bf162 g_vth[16 * 64 * 2048], g_vtl[16 * 64 * 2048];
__device__ __align__(16) bf162 g_yh[T_SEQ * 512],  g_yl[T_SEQ * 512];

// single-instruction bf16x2 pack: .x = a (lo half), .y = b (hi half)
__device__ __forceinline__ bf162 pack2(float a, float b) {
    uint32_t r;
    asm("cvt.rn.bf16x2.f32 %0, %1, %2;" : "=r"(r) : "f"(b), "f"(a));
    return *(bf162*)&r;
}

__device__ __forceinline__ void cpa16(uint32_t dst, const void* src) {
    asm volatile("cp.async.cg.shared.global [%0], [%1], 16;" :: "r"(dst), "l"(src));
}
#define CP_COMMIT() asm volatile("cp.async.commit_group;")
#define CP_WAIT1()  asm volatile("cp.async.wait_group 1;")
#define CP_WAIT0()  asm volatile("cp.async.wait_group 0;")

__device__ __forceinline__ uint32_t smem_u32(const void* p) {
    uint32_t a;
    asm("{ .reg .u64 tmp; cvta.to.shared.u64 tmp, %1; cvt.u32.u64 %0, tmp; }"
        : "=r"(a) : "l"(p));
    return a;
}

__device__ __forceinline__ void ldsm4(uint32_t& r0, uint32_t& r1,
                                      uint32_t& r2, uint32_t& r3, uint32_t a) {
    asm volatile("ldmatrix.sync.aligned.m8n8.x4.shared.b16 {%0,%1,%2,%3}, [%4];"
                 : "=r"(r0), "=r"(r1), "=r"(r2), "=r"(r3) : "r"(a));
}

__device__ __forceinline__ void mma16816(float* d, uint32_t a0, uint32_t a1,
                                         uint32_t a2, uint32_t a3,
                                         uint32_t b0, uint32_t b1) {
    asm volatile("mma.sync.aligned.m16n8k16.row.col.f32.bf16.bf16.f32 "
                 "{%0,%1,%2,%3}, {%4,%5,%6,%7}, {%8,%9}, {%0,%1,%2,%3};\n"
                 : "+f"(d[0]), "+f"(d[1]), "+f"(d[2]), "+f"(d[3])
                 : "r"(a0), "r"(a1), "r"(a2), "r"(a3), "r"(b0), "r"(b1));
}

__device__ __forceinline__ void imma16832(int* d, uint32_t a0, uint32_t a1,
                                          uint32_t a2, uint32_t a3,
                                          uint32_t b0, uint32_t b1) {
    asm volatile("mma.sync.aligned.m16n8k32.row.col.s32.s8.s8.s32 "
                 "{%0,%1,%2,%3}, {%4,%5,%6,%7}, {%8,%9}, {%0,%1,%2,%3};\n"
                 : "+r"(d[0]), "+r"(d[1]), "+r"(d[2]), "+r"(d[3])
                 : "r"(a0), "r"(a1), "r"(a2), "r"(a3), "r"(b0), "r"(b1));
}

// ---------------------------------------------------------------------------
// Per-row int8 two-limb quantization: x = s*(i1 + i2/256), s = rowmax/127.
// One block per row of 1024 floats.
// ---------------------------------------------------------------------------
__device__ __forceinline__ void quant_row(float q0, float q1, float q2, float q3,
                                          uint32_t* o1, uint32_t* o2, size_t idx) {
    int i1[4], i2[4];
    float q[4] = {q0, q1, q2, q3};
#pragma unroll
    for (int j = 0; j < 4; j++) {
        i1[j] = __float2int_rn(q[j]);
        float r = q[j] - (float)i1[j];
        int t2 = __float2int_rn(r * 256.f);
        i2[j] = max(-127, min(127, t2));
    }
    o1[idx] = (uint32_t)(i1[0] & 255) | ((uint32_t)(i1[1] & 255) << 8)
            | ((uint32_t)(i1[2] & 255) << 16) | ((uint32_t)(i1[3] & 255) << 24);
    o2[idx] = (uint32_t)(i2[0] & 255) | ((uint32_t)(i2[1] & 255) << 8)
            | ((uint32_t)(i2[2] & 255) << 16) | ((uint32_t)(i2[3] & 255) << 24);
}

__global__ __launch_bounds__(256)
void quant3_kernel(const float* __restrict__ x, const float* __restrict__ wq,
                   const float* __restrict__ wp,
                   uint32_t* __restrict__ xi1, uint32_t* __restrict__ xi2,
                   uint32_t* __restrict__ wqi1, uint32_t* __restrict__ wqi2,
                   uint32_t* __restrict__ wpi1, uint32_t* __restrict__ wpi2,
                   float* __restrict__ sx, float* __restrict__ swq,
                   float* __restrict__ swp) {
    int rid = blockIdx.x, t = threadIdx.x, row;
    const float* in; uint32_t *o1, *o2; float* sc;
    if (rid < 4096)      { row = rid;        in = x;  o1 = xi1;  o2 = xi2;  sc = sx;  }
    else if (rid < 7168) { row = rid - 4096; in = wq; o1 = wqi1; o2 = wqi2; sc = swq; }
    else                 { row = rid - 7168; in = wp; o1 = wpi1; o2 = wpi2; sc = swp; }
    float4 v = ((const float4*)(in + (size_t)row * 1024))[t];
    float m = fmaxf(fmaxf(fabsf(v.x), fabsf(v.y)), fmaxf(fabsf(v.z), fabsf(v.w)));
#pragma unroll
    for (int off = 16; off; off >>= 1) m = fmaxf(m, __shfl_xor_sync(~0u, m, off));
    __shared__ float wm[8];
    if ((t & 31) == 0) wm[t >> 5] = m;
    __syncthreads();
    float mv = fmaxf(fmaxf(fmaxf(wm[0], wm[1]), fmaxf(wm[2], wm[3])),
                     fmaxf(fmaxf(wm[4], wm[5]), fmaxf(wm[6], wm[7])));
    float s = fmaxf(mv, 1e-20f) * (1.f / 127.f);
    if (t == 0) sc[row] = s;
    float inv = 1.f / s;
    quant_row(v.x * inv, v.y * inv, v.z * inv, v.w * inv, o1, o2,
              (size_t)row * 256 + t);
}

__global__ __launch_bounds__(256)
void quanty_kernel(const bf162* __restrict__ yh, const bf162* __restrict__ yl,
                   uint32_t* __restrict__ yi1, uint32_t* __restrict__ yi2,
                   float* __restrict__ sy) {
    int row = blockIdx.x, t = threadIdx.x;
    bf162 h0 = yh[(size_t)row * 512 + 2 * t], h1 = yh[(size_t)row * 512 + 2 * t + 1];
    bf162 l0 = yl[(size_t)row * 512 + 2 * t], l1 = yl[(size_t)row * 512 + 2 * t + 1];
    float f0 = __bfloat162float(h0.x) + __bfloat162float(l0.x);
    float f1 = __bfloat162float(h0.y) + __bfloat162float(l0.y);
    float f2 = __bfloat162float(h1.x) + __bfloat162float(l1.x);
    float f3 = __bfloat162float(h1.y) + __bfloat162float(l1.y);
    float m = fmaxf(fmaxf(fabsf(f0), fabsf(f1)), fmaxf(fabsf(f2), fabsf(f3)));
#pragma unroll
    for (int off = 16; off; off >>= 1) m = fmaxf(m, __shfl_xor_sync(~0u, m, off));
    __shared__ float wm[8];
    if ((t & 31) == 0) wm[t >> 5] = m;
    __syncthreads();
    float mv = fmaxf(fmaxf(fmaxf(wm[0], wm[1]), fmaxf(wm[2], wm[3])),
                     fmaxf(fmaxf(wm[4], wm[5]), fmaxf(wm[6], wm[7])));
    float s = fmaxf(mv, 1e-20f) * (1.f / 127.f);
    if (t == 0) sy[row] = s;
    float inv = 1.f / s;
    quant_row(f0 * inv, f1 * inv, f2 * inv, f3 * inv, yi1, yi2,
              (size_t)row * 256 + t);
}

// ---------------------------------------------------------------------------
// int8 two-limb GEMM: C = sA sB (i1a i1b + (i1a i2b + i2a i1b)/256) + bias.
// Block 128x64, 8 warps (2m x 4n), warp tile 64x16. BK=64 int8, nk=16.
// 2-stage cp.async pipeline, ldmatrix (b16 == 2x s8), 2 blocks/SM.
// Cols < scale_cols: *0.125.  Cols >= v_cols: transposed into Vth/Vtl.
// ---------------------------------------------------------------------------
#define GST 20
#define ISTAGE_U ((2 * 128 + 2 * 64) * GST)   // Ai1,Ai2(128 rows) Bi1,Bi2(64 rows)
#define ISMEM (2 * ISTAGE_U * 4)

__global__ __launch_bounds__(256, 2)
void gemm_i8(const uint32_t* __restrict__ Ai1, const uint32_t* __restrict__ Ai2,
             const uint32_t* __restrict__ Bi1, const uint32_t* __restrict__ Bi2,
             const float* __restrict__ sA, const float* __restrict__ sB,
             const float* __restrict__ bias, float* __restrict__ Cf,
             bf162* __restrict__ Ch, bf162* __restrict__ Cl,
             bf162* __restrict__ Vth, bf162* __restrict__ Vtl,
             int M, int N, int scale_cols, int v_cols) {
    extern __shared__ uint32_t dsm[];
    const int t = threadIdx.x, lane = t & 31, warp = t >> 5;
    const int g = lane >> 2, qd = lane & 3;
    const int wm = warp & 1, wn = warp >> 1;
    const int m0 = blockIdx.y * 128, n0 = blockIdx.x * 64;
    const uint32_t sbase = smem_u32(dsm);
    const int nk = 16;                         // K=1024, BK=64 int8

    const int lr = lane & 7;
    const uint32_t aro = ((((lane >> 3) & 1) * 8 + lr) * GST + (lane >> 4) * 4) * 4;
    const uint32_t bro = (((lane >> 4) * 8 + lr) * GST + ((lane >> 3) & 1) * 4) * 4;

    int acc1[4][2][4], acc2[4][2][4];
#pragma unroll
    for (int a = 0; a < 4; a++)
#pragma unroll
        for (int b = 0; b < 2; b++)
#pragma unroll
            for (int r = 0; r < 4; r++) { acc1[a][b][r] = 0; acc2[a][b][r] = 0; }

    auto issue = [&](int k) {
        uint32_t so = (uint32_t)(k & 1) * ISTAGE_U;
        int kc = k << 4;                       // 16 u32 per row per iter
#pragma unroll
        for (int l = 0; l < 2; l++) {          // A limbs
            const uint32_t* src = l ? Ai2 : Ai1;
#pragma unroll
            for (int hf = 0; hf < 2; hf++) {
                int w = hf * 256 + t, row = w >> 2, grp = w & 3;
                cpa16(sbase + (so + l * 128 * GST + row * GST + grp * 4) * 4,
                      src + (size_t)(m0 + row) * 256 + kc + grp * 4);
            }
        }
#pragma unroll
        for (int l = 0; l < 2; l++) {          // B limbs
            const uint32_t* src = l ? Bi2 : Bi1;
            int row = t >> 2, grp = t & 3;
            cpa16(sbase + (so + (256 + l * 64) * GST + row * GST + grp * 4) * 4,
                  src + (size_t)(n0 + row) * 256 + kc + grp * 4);
        }
        CP_COMMIT();
    };

    issue(0);
    issue(1);
    for (int k = 0; k < nk; k++) {
        CP_WAIT1();
        __syncthreads();

        const uint32_t stg = sbase + (uint32_t)(k & 1) * ISTAGE_U * 4;
        const uint32_t bA1 = stg + (wm * 64) * GST * 4 + aro;
        const uint32_t bA2 = bA1 + 128 * GST * 4;
        const uint32_t bB1 = stg + 256 * GST * 4 + (wn * 16) * GST * 4 + bro;
        const uint32_t bB2 = bB1 + 64 * GST * 4;
#pragma unroll
        for (int kk = 0; kk < 2; kk++) {       // two k=32 chunks
            const uint32_t ko = kk * 32;       // 8 u32 = 32 bytes
            uint32_t a1[4][4], a2[4][4], b1[4], b2[4];
#pragma unroll
            for (int fm = 0; fm < 4; fm++) {
                ldsm4(a1[fm][0], a1[fm][1], a1[fm][2], a1[fm][3],
                      bA1 + fm * 16 * GST * 4 + ko);
                ldsm4(a2[fm][0], a2[fm][1], a2[fm][2], a2[fm][3],
                      bA2 + fm * 16 * GST * 4 + ko);
            }
            ldsm4(b1[0], b1[1], b1[2], b1[3], bB1 + ko);
            ldsm4(b2[0], b2[1], b2[2], b2[3], bB2 + ko);
            // term-major: i1*i1 -> acc1; i1*i2 -> acc2; i2*i1 -> acc2
#pragma unroll
            for (int fn = 0; fn < 2; fn++)
#pragma unroll
                for (int fm = 0; fm < 4; fm++)
                    imma16832(acc1[fm][fn], a1[fm][0], a1[fm][1], a1[fm][2], a1[fm][3],
                              b1[2 * fn], b1[2 * fn + 1]);
#pragma unroll
            for (int fn = 0; fn < 2; fn++)
#pragma unroll
                for (int fm = 0; fm < 4; fm++)
                    imma16832(acc2[fm][fn], a1[fm][0], a1[fm][1], a1[fm][2], a1[fm][3],
                              b2[2 * fn], b2[2 * fn + 1]);
#pragma unroll
            for (int fn = 0; fn < 2; fn++)
#pragma unroll
                for (int fm = 0; fm < 4; fm++)
                    imma16832(acc2[fm][fn], a2[fm][0], a2[fm][1], a2[fm][2], a2[fm][3],
                              b1[2 * fn], b1[2 * fn + 1]);
        }
        __syncthreads();
        if (k + 2 < nk) issue(k + 2); else CP_COMMIT();
    }

    const float sc = (n0 < scale_cols) ? 0.125f : 1.0f;   // tile-uniform
    const bool vtile = (n0 >= v_cols);                     // tile-uniform
#pragma unroll
    for (int fm = 0; fm < 4; fm++) {
        int row = m0 + wm * 64 + fm * 16 + g;
        float sa0 = sA[row], sa1 = sA[row + 8];
#pragma unroll
        for (int fn = 0; fn < 2; fn++) {
            int col = n0 + wn * 16 + fn * 8 + 2 * qd;
            float sb0 = sB[col], sb1 = sB[col + 1];
            float b0 = bias[col], b1v = bias[col + 1];
            float d0 = sa0 * sb0 * ((float)acc1[fm][fn][0] + (float)acc2[fm][fn][0] * (1.f/256.f));
            float d1 = sa0 * sb1 * ((float)acc1[fm][fn][1] + (float)acc2[fm][fn][1] * (1.f/256.f));
            float d2 = sa1 * sb0 * ((float)acc1[fm][fn][2] + (float)acc2[fm][fn][2] * (1.f/256.f));
            float d3 = sa1 * sb1 * ((float)acc1[fm][fn][3] + (float)acc2[fm][fn][3] * (1.f/256.f));
            float v0 = (d0 + b0) * sc, v1 = (d1 + b1v) * sc;
            float v2 = (d2 + b0) * sc, v3 = (d3 + b1v) * sc;
            if (Cf) {
                float2 p0 = {v0, v1}, p1 = {v2, v3};
                *(float2*)&Cf[(size_t)row * N + col] = p0;
                *(float2*)&Cf[(size_t)(row + 8) * N + col] = p1;
            } else if (!vtile) {
                size_t c0 = (size_t)row * (N >> 1) + (col >> 1);
                size_t c1 = (size_t)(row + 8) * (N >> 1) + (col >> 1);
                bf162 h0 = pack2(v0, v1), h1 = pack2(v2, v3);
                Ch[c0] = h0; Ch[c1] = h1;
                Cl[c0] = pack2(v0 - __bfloat162float(h0.x), v1 - __bfloat162float(h0.y));
                Cl[c1] = pack2(v2 - __bfloat162float(h1.x), v3 - __bfloat162float(h1.y));
            } else {
                // transposed V store: vt[(col - v_cols)][token-pair]
                float e0 = __shfl_xor_sync(0xffffffffu, v0, 4);
                float e1 = __shfl_xor_sync(0xffffffffu, v1, 4);
                float e2 = __shfl_xor_sync(0xffffffffu, v2, 4);
                float e3 = __shfl_xor_sync(0xffffffffu, v3, 4);
                int colV = col - v_cols;
                if ((g & 1) == 0) {
                    size_t base = (size_t)colV * 2048 + (row >> 1);
                    bf162 h0 = pack2(v0, e0), h1 = pack2(v2, e2);
                    Vth[base] = h0; Vth[base + 4] = h1;
                    Vtl[base]     = pack2(v0 - __bfloat162float(h0.x), e0 - __bfloat162float(h0.y));
                    Vtl[base + 4] = pack2(v2 - __bfloat162float(h1.x), e2 - __bfloat162float(h1.y));
                } else {
                    size_t base = (size_t)(colV + 1) * 2048 + ((row - 1) >> 1);
                    bf162 h0 = pack2(e1, v1), h1 = pack2(e3, v3);
                    Vth[base] = h0; Vth[base + 4] = h1;
                    Vtl[base]     = pack2(e1 - __bfloat162float(h0.x), v1 - __bfloat162float(h0.y));
                    Vtl[base + 4] = pack2(e3 - __bfloat162float(h1.x), v3 - __bfloat162float(h1.y));
                }
            }
        }
    }
}

// ---------------------------------------------------------------------------
// Flash attention (causal) -- unchanged from the passing R13 kernel.
// ---------------------------------------------------------------------------
#define AST 36
#define AQ_U   (2 * 64 * AST)
#define AKV_U  (4 * 64 * AST)
#define ATTN_SMEM ((AQ_U + 2 * AKV_U) * 4)

__global__ __launch_bounds__(128, 2)
void attn_mma(const bf162* __restrict__ qh, const bf162* __restrict__ ql,
              const bf162* __restrict__ vth, const bf162* __restrict__ vtl,
              bf162* __restrict__ yh, bf162* __restrict__ yl) {
    extern __shared__ uint32_t dsm[];
    const int t = threadIdx.x, lane = t & 31, warp = t >> 5;
    const int g = lane >> 2, qd = lane & 3;
    const int h = blockIdx.y, qi = 63 - blockIdx.x, q0 = qi * 64;
    const uint32_t sbase = smem_u32(dsm);
    const uint32_t* Q32h = (const uint32_t*)qh;
    const uint32_t* Q32l = (const uint32_t*)ql;
    const uint32_t* V32h = (const uint32_t*)vth;
    const uint32_t* V32l = (const uint32_t*)vtl;

    const int lr = lane & 7;
    const uint32_t aro = ((((lane >> 3) & 1) * 8 + lr) * AST + (lane >> 4) * 4) * 4;
    const uint32_t bro = (((lane >> 4) * 8 + lr) * AST + ((lane >> 3) & 1) * 4) * 4;

#pragma unroll
    for (int a = 0; a < 2; a++)
#pragma unroll
        for (int hf = 0; hf < 4; hf++) {
            int w = hf * 128 + t, row = w >> 3, grp = w & 7;
            const uint32_t* gp = (a ? Q32l : Q32h) + (size_t)(q0 + row) * 1536 + h * 32 + grp * 4;
            cpa16(sbase + (a * 64 * AST + row * AST + grp * 4) * 4, gp);
        }

    auto issueKV = [&](int kt) {
        uint32_t so = AQ_U + (uint32_t)(kt & 1) * AKV_U;
        int k0 = kt * 64;
#pragma unroll
        for (int a = 0; a < 4; a++)
#pragma unroll
            for (int hf = 0; hf < 4; hf++) {
                int w = hf * 128 + t, row = w >> 3, grp = w & 7;
                const uint32_t* gp;
                if (a == 0)      gp = Q32h + (size_t)(k0 + row) * 1536 + 512 + h * 32 + grp * 4;
                else if (a == 1) gp = Q32l + (size_t)(k0 + row) * 1536 + 512 + h * 32 + grp * 4;
                else if (a == 2) gp = V32h + (size_t)(h * 64 + row) * 2048 + kt * 32 + grp * 4;
                else             gp = V32l + (size_t)(h * 64 + row) * 2048 + kt * 32 + grp * 4;
                cpa16(sbase + (so + a * 64 * AST + row * AST + grp * 4) * 4, gp);
            }
    };

    issueKV(0); CP_COMMIT();
    CP_WAIT0();
    __syncthreads();

    const uint32_t bQh = sbase + (warp * 16) * AST * 4 + aro;
    const uint32_t bQl = bQh + 64 * AST * 4;
    uint32_t aqh[4][4], aql[4][4];
#pragma unroll
    for (int kk = 0; kk < 4; kk++) {
        ldsm4(aqh[kk][0], aqh[kk][1], aqh[kk][2], aqh[kk][3], bQh + kk * 32);
        ldsm4(aql[kk][0], aql[kk][1], aql[kk][2], aql[kk][3], bQl + kk * 32);
    }

    float o[8][4];
#pragma unroll
    for (int fn = 0; fn < 8; fn++)
#pragma unroll
        for (int r = 0; r < 4; r++) o[fn][r] = 0.f;
    float l0p = 0.f, l1p = 0.f;
    uint32_t pah[4][4], pal[4][4];

    const int rA = warp * 16 + g;
    const int row0g = q0 + rA, row1g = row0g + 8;

    for (int kt = 0; kt <= qi; kt++) {
        const uint32_t stgC = sbase + (AQ_U + (kt & 1) * AKV_U) * 4;
        const uint32_t bKh = stgC + bro;
        const uint32_t bKl = bKh + 64 * AST * 4;
        const uint32_t stgP = sbase + (AQ_U + ((kt + 1) & 1) * AKV_U) * 4;
        const uint32_t bVh = stgP + 2 * 64 * AST * 4 + bro;
        const uint32_t bVl = bVh + 64 * AST * 4;
        const int k0 = kt * 64;

        float s[8][4];
#pragma unroll
        for (int fn = 0; fn < 8; fn++)
#pragma unroll
            for (int r = 0; r < 4; r++) s[fn][r] = 0.f;
#pragma unroll
        for (int kk = 0; kk < 4; kk++) {
            const uint32_t ko = kk * 32;
#pragma unroll
            for (int fp = 0; fp < 4; fp++) {
                uint32_t kh0, kh1, kh2, kh3, kl0, kl1, kl2, kl3;
                ldsm4(kh0, kh1, kh2, kh3, bKh + fp * 16 * AST * 4 + ko);
                ldsm4(kl0, kl1, kl2, kl3, bKl + fp * 16 * AST * 4 + ko);
                mma16816(s[2*fp],   aqh[kk][0], aqh[kk][1], aqh[kk][2], aqh[kk][3], kh0, kh1);
                mma16816(s[2*fp+1], aqh[kk][0], aqh[kk][1], aqh[kk][2], aqh[kk][3], kh2, kh3);
                mma16816(s[2*fp],   aqh[kk][0], aqh[kk][1], aqh[kk][2], aqh[kk][3], kl0, kl1);
                mma16816(s[2*fp+1], aqh[kk][0], aqh[kk][1], aqh[kk][2], aqh[kk][3], kl2, kl3);
                mma16816(s[2*fp],   aql[kk][0], aql[kk][1], aql[kk][2], aql[kk][3], kh0, kh1);
                mma16816(s[2*fp+1], aql[kk][0], aql[kk][1], aql[kk][2], aql[kk][3], kh2, kh3);
            }
        }

        if (kt > 0) {
#pragma unroll
            for (int j = 0; j < 4; j++) {
#pragma unroll
                for (int fp = 0; fp < 4; fp++) {
                    uint32_t vh0, vh1, vh2, vh3, vl0, vl1, vl2, vl3;
                    ldsm4(vh0, vh1, vh2, vh3, bVh + fp * 16 * AST * 4 + j * 32);
                    ldsm4(vl0, vl1, vl2, vl3, bVl + fp * 16 * AST * 4 + j * 32);
                    mma16816(o[2*fp],   pah[j][0], pah[j][1], pah[j][2], pah[j][3], vh0, vh1);
                    mma16816(o[2*fp+1], pah[j][0], pah[j][1], pah[j][2], pah[j][3], vh2, vh3);
                    mma16816(o[2*fp],   pah[j][0], pah[j][1], pah[j][2], pah[j][3], vl0, vl1);
                    mma16816(o[2*fp+1], pah[j][0], pah[j][1], pah[j][2], pah[j][3], vl2, vl3);
                    mma16816(o[2*fp],   pal[j][0], pal[j][1], pal[j][2], pal[j][3], vh0, vh1);
                    mma16816(o[2*fp+1], pal[j][0], pal[j][1], pal[j][2], pal[j][3], vh2, vh3);
                }
            }
        }

        __syncthreads();
        if (kt + 1 <= qi) { issueKV(kt + 1); CP_COMMIT(); }

        if (kt == qi) {
#pragma unroll
            for (int fn = 0; fn < 8; fn++) {
                int cg = k0 + fn * 8 + 2 * qd;
                if (cg > row0g)     s[fn][0] = -INFINITY;
                if (cg + 1 > row0g) s[fn][1] = -INFINITY;
                if (cg > row1g)     s[fn][2] = -INFINITY;
                if (cg + 1 > row1g) s[fn][3] = -INFINITY;
            }
        }
#pragma unroll
        for (int fn = 0; fn < 8; fn++) {
            s[fn][0] = __expf(s[fn][0]); s[fn][1] = __expf(s[fn][1]);
            s[fn][2] = __expf(s[fn][2]); s[fn][3] = __expf(s[fn][3]);
            l0p += s[fn][0] + s[fn][1];
            l1p += s[fn][2] + s[fn][3];
        }
#pragma unroll
        for (int j = 0; j < 4; j++) {
            bf162 h0 = pack2(s[2*j][0],   s[2*j][1]);
            bf162 h1 = pack2(s[2*j][2],   s[2*j][3]);
            bf162 h2 = pack2(s[2*j+1][0], s[2*j+1][1]);
            bf162 h3 = pack2(s[2*j+1][2], s[2*j+1][3]);
            bf162 e0 = pack2(s[2*j][0] - __bfloat162float(h0.x),   s[2*j][1] - __bfloat162float(h0.y));
            bf162 e1 = pack2(s[2*j][2] - __bfloat162float(h1.x),   s[2*j][3] - __bfloat162float(h1.y));
            bf162 e2 = pack2(s[2*j+1][0] - __bfloat162float(h2.x), s[2*j+1][1] - __bfloat162float(h2.y));
            bf162 e3 = pack2(s[2*j+1][2] - __bfloat162float(h3.x), s[2*j+1][3] - __bfloat162float(h3.y));
            pah[j][0] = *(uint32_t*)&h0; pah[j][1] = *(uint32_t*)&h1;
            pah[j][2] = *(uint32_t*)&h2; pah[j][3] = *(uint32_t*)&h3;
            pal[j][0] = *(uint32_t*)&e0; pal[j][1] = *(uint32_t*)&e1;
            pal[j][2] = *(uint32_t*)&e2; pal[j][3] = *(uint32_t*)&e3;
        }

        if (kt + 1 <= qi) {
            CP_WAIT0();
            __syncthreads();
        }
    }

    {
        const uint32_t stgP = sbase + (AQ_U + (qi & 1) * AKV_U) * 4;
        const uint32_t bVh = stgP + 2 * 64 * AST * 4 + bro;
        const uint32_t bVl = bVh + 64 * AST * 4;
#pragma unroll
        for (int j = 0; j < 4; j++) {
#pragma unroll
            for (int fp = 0; fp < 4; fp++) {
                uint32_t vh0, vh1, vh2, vh3, vl0, vl1, vl2, vl3;
                ldsm4(vh0, vh1, vh2, vh3, bVh + fp * 16 * AST * 4 + j * 32);
                ldsm4(vl0, vl1, vl2, vl3, bVl + fp * 16 * AST * 4 + j * 32);
                mma16816(o[2*fp],   pah[j][0], pah[j][1], pah[j][2], pah[j][3], vh0, vh1);
                mma16816(o[2*fp+1], pah[j][0], pah[j][1], pah[j][2], pah[j][3], vh2, vh3);
                mma16816(o[2*fp],   pah[j][0], pah[j][1], pah[j][2], pah[j][3], vl0, vl1);
                mma16816(o[2*fp+1], pah[j][0], pah[j][1], pah[j][2], pah[j][3], vl2, vl3);
                mma16816(o[2*fp],   pal[j][0], pal[j][1], pal[j][2], pal[j][3], vh0, vh1);
                mma16816(o[2*fp+1], pal[j][0], pal[j][1], pal[j][2], pal[j][3], vh2, vh3);
            }
        }
    }

#pragma unroll
    for (int off = 1; off <= 2; off <<= 1) {
        l0p += __shfl_xor_sync(0xffffffffu, l0p, off);
        l1p += __shfl_xor_sync(0xffffffffu, l1p, off);
    }

    float i0 = 1.f / l0p, i1 = 1.f / l1p;
#pragma unroll
    for (int fn = 0; fn < 8; fn++) {
        int col = h * 64 + fn * 8 + 2 * qd;
        float v0 = o[fn][0] * i0, v1 = o[fn][1] * i0;
        float v2 = o[fn][2] * i1, v3 = o[fn][3] * i1;
        size_t p0 = (size_t)row0g * 512 + (col >> 1);
        size_t p1 = (size_t)row1g * 512 + (col >> 1);
        bf162 h0 = pack2(v0, v1), h1 = pack2(v2, v3);
        yh[p0] = h0; yh[p1] = h1;
        yl[p0] = pack2(v0 - __bfloat162float(h0.x), v1 - __bfloat162float(h0.y));
        yl[p1] = pack2(v2 - __bfloat162float(h1.x), v3 - __bfloat162float(h1.y));
    }
}

// ---------------------------------------------------------------------------
extern "C" void kernel_launch(void* const* d_in, const int* in_sizes, int n_in,
                              void* d_out, int out_size) {
    const float* x     = (const float*)d_in[0];
    const float* Wqkv  = (const float*)d_in[1];
    const float* bqkv  = (const float*)d_in[2];
    const float* Wproj = (const float*)d_in[3];
    const float* bproj = (const float*)d_in[4];
    float* out = (float*)d_out;

    uint32_t *xi1, *xi2, *wqi1, *wqi2, *wpi1, *wpi2, *yi1, *yi2;
    float *sx, *swq, *swp, *sy;
    bf162 *qh, *ql, *vth, *vtl, *yh, *yl;
    cudaGetSymbolAddress((void**)&xi1, g_xi1);   cudaGetSymbolAddress((void**)&xi2, g_xi2);
    cudaGetSymbolAddress((void**)&wqi1, g_wqi1); cudaGetSymbolAddress((void**)&wqi2, g_wqi2);
    cudaGetSymbolAddress((void**)&wpi1, g_wpi1); cudaGetSymbolAddress((void**)&wpi2, g_wpi2);
    cudaGetSymbolAddress((void**)&yi1, g_yi1);   cudaGetSymbolAddress((void**)&yi2, g_yi2);
    cudaGetSymbolAddress((void**)&sx, g_sx);     cudaGetSymbolAddress((void**)&swq, g_swq);
    cudaGetSymbolAddress((void**)&swp, g_swp);   cudaGetSymbolAddress((void**)&sy, g_sy);
    cudaGetSymbolAddress((void**)&qh, g_qh);     cudaGetSymbolAddress((void**)&ql, g_ql);
    cudaGetSymbolAddress((void**)&vth, g_vth);   cudaGetSymbolAddress((void**)&vtl, g_vtl);
    cudaGetSymbolAddress((void**)&yh, g_yh);     cudaGetSymbolAddress((void**)&yl, g_yl);

    cudaFuncSetAttribute(gemm_i8, cudaFuncAttributeMaxDynamicSharedMemorySize, ISMEM);
    cudaFuncSetAttribute(attn_mma, cudaFuncAttributeMaxDynamicSharedMemorySize, ATTN_SMEM);

    quant3_kernel<<<8192, 256>>>(x, Wqkv, Wproj, xi1, xi2, wqi1, wqi2,
                                 wpi1, wpi2, sx, swq, swp);
    // QKV: Q cols scaled 1/8, V cols (>=2048) transposed into vth/vtl
    gemm_i8<<<dim3(48, 32), 256, ISMEM>>>(xi1, xi2, wqi1, wqi2, sx, swq, bqkv,
                                          nullptr, qh, ql, vth, vtl,
                                          T_SEQ, 3072, 1024, 2048);
    attn_mma<<<dim3(64, 16), 128, ATTN_SMEM>>>(qh, ql, vth, vtl, yh, yl);
    quanty_kernel<<<4096, 256>>>(yh, yl, yi1, yi2, sy);
    gemm_i8<<<dim3(16, 32), 256, ISMEM>>>(yi1, yi2, wpi1, wpi2, sy, swp, bproj,
                                          out, nullptr, nullptr, nullptr, nullptr,
                                          T_SEQ, 1024, 0, 1 << 30);
}

// round 16
// speedup vs baseline: 1.0584x; 1.0584x over previous
#include <cuda_runtime.h>
#include <cuda_bf16.h>
#include <stdint.h>
#include <math.h>

typedef __nv_bfloat16  bf16;
typedef __nv_bfloat162 bf162;

#define T_SEQ 4096

// Scratch (device globals; no allocation allowed)
__device__ __align__(16) bf162 g_xh[T_SEQ * 512],  g_xl[T_SEQ * 512];
__device__ __align__(16) bf162 g_wqh[3072 * 512],  g_wql[3072 * 512];
__device__ __align__(16) bf162 g_wph[1024 * 512],  g_wpl[1024 * 512];
__device__ __align__(16) bf162 g_qh[T_SEQ * 1536], g_ql[T_SEQ * 1536];
__device__ __align__(16) bf162 g_vth[16 * 64 * 2048], g_vtl[16 * 64 * 2048];
__device__ __align__(16) bf162 g_yh[T_SEQ * 512],  g_yl[T_SEQ * 512];

// single-instruction bf16x2 pack: .x = a (lo half), .y = b (hi half)
__device__ __forceinline__ bf162 pack2(float a, float b) {
    uint32_t r;
    asm("cvt.rn.bf16x2.f32 %0, %1, %2;" : "=r"(r) : "f"(b), "f"(a));
    return *(bf162*)&r;
}

__device__ __forceinline__ void cpa16(uint32_t dst, const void* src) {
    asm volatile("cp.async.cg.shared.global [%0], [%1], 16;" :: "r"(dst), "l"(src));
}
#define CP_COMMIT() asm volatile("cp.async.commit_group;")
#define CP_WAIT1()  asm volatile("cp.async.wait_group 1;")
#define CP_WAIT0()  asm volatile("cp.async.wait_group 0;")

__device__ __forceinline__ uint32_t smem_u32(const void* p) {
    uint32_t a;
    asm("{ .reg .u64 tmp; cvta.to.shared.u64 tmp, %1; cvt.u32.u64 %0, tmp; }"
        : "=r"(a) : "l"(p));
    return a;
}

// ldmatrix x4: r0..r3 <- four 8x8 b16 matrices, per-lane row addresses
__device__ __forceinline__ void ldsm4(uint32_t& r0, uint32_t& r1,
                                      uint32_t& r2, uint32_t& r3, uint32_t a) {
    asm volatile("ldmatrix.sync.aligned.m8n8.x4.shared.b16 {%0,%1,%2,%3}, [%4];"
                 : "=r"(r0), "=r"(r1), "=r"(r2), "=r"(r3) : "r"(a));
}

// Fused fp32 -> (bf16 hi, bf16 lo) split for x, W_qkv, W_proj (one launch)
#define NPX (T_SEQ * 512)
#define NPQ (3072 * 512)
#define NPP (1024 * 512)
__global__ void split3_kernel(const float* __restrict__ x,
                              const float* __restrict__ wq,
                              const float* __restrict__ wp,
                              bf162* __restrict__ xh, bf162* __restrict__ xl,
                              bf162* __restrict__ wqh, bf162* __restrict__ wql,
                              bf162* __restrict__ wph, bf162* __restrict__ wpl) {
    int i = blockIdx.x * 256 + threadIdx.x;
    const float* in; bf162 *ho, *lo;
    if (i < NPX)            { in = x;  ho = xh;  lo = xl; }
    else if (i < NPX + NPQ) { i -= NPX; in = wq; ho = wqh; lo = wql; }
    else                    { i -= NPX + NPQ; in = wp; ho = wph; lo = wpl; }
    float2 v = ((const float2*)in)[i];
    bf162 h = pack2(v.x, v.y);
    ho[i] = h;
    lo[i] = pack2(v.x - __bfloat162float(h.x), v.y - __bfloat162float(h.y));
}

__device__ __forceinline__ void mma16816(float* d, uint32_t a0, uint32_t a1,
                                         uint32_t a2, uint32_t a3,
                                         uint32_t b0, uint32_t b1) {
    asm volatile("mma.sync.aligned.m16n8k16.row.col.f32.bf16.bf16.f32 "
                 "{%0,%1,%2,%3}, {%4,%5,%6,%7}, {%8,%9}, {%0,%1,%2,%3};\n"
                 : "+f"(d[0]), "+f"(d[1]), "+f"(d[2]), "+f"(d[3])
                 : "r"(a0), "r"(a1), "r"(a2), "r"(a3), "r"(b0), "r"(b1));
}

// ---------------------------------------------------------------------------
// GEMM bf16x3, 2-stage cp.async pipeline, ldmatrix, 2 blocks/SM.
// Term-major MMA sweeps (16 indep accumulators per sweep).
// C[M,N] = (Ah+Al)(Bh+Bl)^T + bias.  Kp = K/2 pairs, BK=32.
// Cols < scale_cols: *0.125 (exact pow2).  Cols >= v_cols: written TRANSPOSED
// into Vth/Vtl as vt[col - v_cols][token-pair] (fuses the V transpose).
// ---------------------------------------------------------------------------
#define GST 20
#define GSTAGE_U (4 * 128 * GST)
#define GSMEM (2 * GSTAGE_U * 4)

__global__ __launch_bounds__(256, 2)
void gemm_bf16x3(const bf162* __restrict__ Ah_, const bf162* __restrict__ Al_,
                 const bf162* __restrict__ Bh_, const bf162* __restrict__ Bl_,
                 const float* __restrict__ bias, float* __restrict__ Cf,
                 bf162* __restrict__ Ch, bf162* __restrict__ Cl,
                 bf162* __restrict__ Vth, bf162* __restrict__ Vtl,
                 int M, int N, int Kp, int scale_cols, int v_cols) {
    extern __shared__ uint32_t dsm[];
    const int t = threadIdx.x, lane = t & 31, warp = t >> 5;
    const int g = lane >> 2, qd = lane & 3;
    const int wm = warp & 1, wn = warp >> 1;
    const int m0 = blockIdx.y * 128, n0 = blockIdx.x * 128;
    const uint32_t* src[4] = {(const uint32_t*)Ah_, (const uint32_t*)Al_,
                              (const uint32_t*)Bh_, (const uint32_t*)Bl_};
    const uint32_t sbase = smem_u32(dsm);
    const int nk = Kp >> 4;

    const int lr = lane & 7;
    const uint32_t aro = ((((lane >> 3) & 1) * 8 + lr) * GST + (lane >> 4) * 4) * 4;
    const uint32_t bro = (((lane >> 4) * 8 + lr) * GST + ((lane >> 3) & 1) * 4) * 4;

    float acc[4][4][4];
#pragma unroll
    for (int a = 0; a < 4; a++)
#pragma unroll
        for (int b = 0; b < 4; b++)
#pragma unroll
            for (int r = 0; r < 4; r++) acc[a][b][r] = 0.f;

    auto issue = [&](int k) {
        uint32_t so = (uint32_t)(k & 1) * GSTAGE_U;
        int kp0 = k << 4;
#pragma unroll
        for (int a = 0; a < 4; a++) {
            int rbase = (a < 2) ? m0 : n0;
#pragma unroll
            for (int hf = 0; hf < 2; hf++) {
                int w = hf * 256 + t, row = w >> 2, grp = w & 3;
                const uint32_t* gp = src[a] + (size_t)(rbase + row) * Kp + kp0 + grp * 4;
                cpa16(sbase + (so + a * 128 * GST + row * GST + grp * 4) * 4, gp);
            }
        }
        CP_COMMIT();
    };

    issue(0);
    issue(1);
    for (int k = 0; k < nk; k++) {
        CP_WAIT1();
        __syncthreads();

        const uint32_t stg = sbase + (uint32_t)(k & 1) * GSTAGE_U * 4;
        const uint32_t bAh = stg + (wm * 64) * GST * 4 + aro;
        const uint32_t bAl = bAh + 128 * GST * 4;
        const uint32_t bBh = stg + 2 * 128 * GST * 4 + (wn * 32) * GST * 4 + bro;
        const uint32_t bBl = bBh + 128 * GST * 4;
#pragma unroll
        for (int kk = 0; kk < 2; kk++) {
            const uint32_t ko = kk * 32;
            uint32_t ah[4][4], al[4][4], bh[2][4], bl[2][4];
#pragma unroll
            for (int fm = 0; fm < 4; fm++) {
                ldsm4(ah[fm][0], ah[fm][1], ah[fm][2], ah[fm][3],
                      bAh + fm * 16 * GST * 4 + ko);
                ldsm4(al[fm][0], al[fm][1], al[fm][2], al[fm][3],
                      bAl + fm * 16 * GST * 4 + ko);
            }
#pragma unroll
            for (int fp = 0; fp < 2; fp++) {
                ldsm4(bh[fp][0], bh[fp][1], bh[fp][2], bh[fp][3],
                      bBh + fp * 16 * GST * 4 + ko);
                ldsm4(bl[fp][0], bl[fp][1], bl[fp][2], bl[fp][3],
                      bBl + fp * 16 * GST * 4 + ko);
            }
            // term-major sweeps: all hh, then hl, then lh (16 indep accs each)
#pragma unroll
            for (int fp = 0; fp < 2; fp++)
#pragma unroll
                for (int hf = 0; hf < 2; hf++)
#pragma unroll
                    for (int fm = 0; fm < 4; fm++)
                        mma16816(acc[fm][2*fp+hf], ah[fm][0], ah[fm][1], ah[fm][2], ah[fm][3],
                                 bh[fp][2*hf], bh[fp][2*hf+1]);
#pragma unroll
            for (int fp = 0; fp < 2; fp++)
#pragma unroll
                for (int hf = 0; hf < 2; hf++)
#pragma unroll
                    for (int fm = 0; fm < 4; fm++)
                        mma16816(acc[fm][2*fp+hf], ah[fm][0], ah[fm][1], ah[fm][2], ah[fm][3],
                                 bl[fp][2*hf], bl[fp][2*hf+1]);
#pragma unroll
            for (int fp = 0; fp < 2; fp++)
#pragma unroll
                for (int hf = 0; hf < 2; hf++)
#pragma unroll
                    for (int fm = 0; fm < 4; fm++)
                        mma16816(acc[fm][2*fp+hf], al[fm][0], al[fm][1], al[fm][2], al[fm][3],
                                 bh[fp][2*hf], bh[fp][2*hf+1]);
        }
        __syncthreads();
        if (k + 2 < nk) issue(k + 2); else CP_COMMIT();
    }

    const float sc = (n0 < scale_cols) ? 0.125f : 1.0f;   // tile-uniform
    const bool vtile = (n0 >= v_cols);                     // tile-uniform
#pragma unroll
    for (int fm = 0; fm < 4; fm++)
#pragma unroll
        for (int fn = 0; fn < 4; fn++) {
            int row = m0 + wm * 64 + fm * 16 + g;
            int col = n0 + wn * 32 + fn * 8 + 2 * qd;
            float b0 = bias[col], b1 = bias[col + 1];
            float v0 = (acc[fm][fn][0] + b0) * sc, v1 = (acc[fm][fn][1] + b1) * sc;
            float v2 = (acc[fm][fn][2] + b0) * sc, v3 = (acc[fm][fn][3] + b1) * sc;
            if (Cf) {
                float2 p0 = {v0, v1}, p1 = {v2, v3};
                *(float2*)&Cf[(size_t)row * N + col] = p0;
                *(float2*)&Cf[(size_t)(row + 8) * N + col] = p1;
            } else if (!vtile) {
                size_t c0 = (size_t)row * (N >> 1) + (col >> 1);
                size_t c1 = (size_t)(row + 8) * (N >> 1) + (col >> 1);
                bf162 h0 = pack2(v0, v1), h1 = pack2(v2, v3);
                Ch[c0] = h0; Ch[c1] = h1;
                Cl[c0] = pack2(v0 - __bfloat162float(h0.x), v1 - __bfloat162float(h0.y));
                Cl[c1] = pack2(v2 - __bfloat162float(h1.x), v3 - __bfloat162float(h1.y));
            } else {
                // transposed V store: vt[(col - v_cols)][token-pair]
                float e0 = __shfl_xor_sync(0xffffffffu, v0, 4);
                float e1 = __shfl_xor_sync(0xffffffffu, v1, 4);
                float e2 = __shfl_xor_sync(0xffffffffu, v2, 4);
                float e3 = __shfl_xor_sync(0xffffffffu, v3, 4);
                int colV = col - v_cols;
                if ((g & 1) == 0) {
                    size_t base = (size_t)colV * 2048 + (row >> 1);
                    bf162 h0 = pack2(v0, e0), h1 = pack2(v2, e2);
                    Vth[base] = h0; Vth[base + 4] = h1;
                    Vtl[base]     = pack2(v0 - __bfloat162float(h0.x), e0 - __bfloat162float(h0.y));
                    Vtl[base + 4] = pack2(v2 - __bfloat162float(h1.x), e2 - __bfloat162float(h1.y));
                } else {
                    size_t base = (size_t)(colV + 1) * 2048 + ((row - 1) >> 1);
                    bf162 h0 = pack2(e1, v1), h1 = pack2(e3, v3);
                    Vth[base] = h0; Vth[base + 4] = h1;
                    Vtl[base]     = pack2(e1 - __bfloat162float(h0.x), v1 - __bfloat162float(h0.y));
                    Vtl[base + 4] = pack2(e3 - __bfloat162float(h1.x), v3 - __bfloat162float(h1.y));
                }
            }
        }
}

// ---------------------------------------------------------------------------
// Flash attention (causal), bf16x3 mma, ldmatrix, q-tile 64 rows, 4 warps,
// 2-stage cp.async K/V pipeline, 2 blocks/SM.
// PV deferred one tile: each iter fronts S(kt)+PV(kt-1) as one independent
// MMA burst; softmax(kt) overlaps the KV(kt+1) load; wait_group 0 at the
// consume point (issue distance is 1 with a 2-stage buffer).
// ---------------------------------------------------------------------------
#define AST 36
#define AQ_U   (2 * 64 * AST)    // Q hi + lo (64 rows)
#define AKV_U  (4 * 64 * AST)    // per stage: Kh, Kl, Vh, Vl
#define ATTN_SMEM ((AQ_U + 2 * AKV_U) * 4)

__global__ __launch_bounds__(128, 2)
void attn_mma(const bf162* __restrict__ qh, const bf162* __restrict__ ql,
              const bf162* __restrict__ vth, const bf162* __restrict__ vtl,
              bf162* __restrict__ yh, bf162* __restrict__ yl) {
    extern __shared__ uint32_t dsm[];
    const int t = threadIdx.x, lane = t & 31, warp = t >> 5;
    const int g = lane >> 2, qd = lane & 3;
    const int h = blockIdx.y, qi = 63 - blockIdx.x, q0 = qi * 64;
    const uint32_t sbase = smem_u32(dsm);
    const uint32_t* Q32h = (const uint32_t*)qh;
    const uint32_t* Q32l = (const uint32_t*)ql;
    const uint32_t* V32h = (const uint32_t*)vth;
    const uint32_t* V32l = (const uint32_t*)vtl;

    const int lr = lane & 7;
    const uint32_t aro = ((((lane >> 3) & 1) * 8 + lr) * AST + (lane >> 4) * 4) * 4;
    const uint32_t bro = (((lane >> 4) * 8 + lr) * AST + ((lane >> 3) & 1) * 4) * 4;

    // stage Q (64 rows x 32 pairs, hi+lo)
#pragma unroll
    for (int a = 0; a < 2; a++)
#pragma unroll
        for (int hf = 0; hf < 4; hf++) {
            int w = hf * 128 + t, row = w >> 3, grp = w & 7;
            const uint32_t* gp = (a ? Q32l : Q32h) + (size_t)(q0 + row) * 1536 + h * 32 + grp * 4;
            cpa16(sbase + (a * 64 * AST + row * AST + grp * 4) * 4, gp);
        }

    auto issueKV = [&](int kt) {
        uint32_t so = AQ_U + (uint32_t)(kt & 1) * AKV_U;
        int k0 = kt * 64;
#pragma unroll
        for (int a = 0; a < 4; a++)
#pragma unroll
            for (int hf = 0; hf < 4; hf++) {
                int w = hf * 128 + t, row = w >> 3, grp = w & 7;
                const uint32_t* gp;
                if (a == 0)      gp = Q32h + (size_t)(k0 + row) * 1536 + 512 + h * 32 + grp * 4;
                else if (a == 1) gp = Q32l + (size_t)(k0 + row) * 1536 + 512 + h * 32 + grp * 4;
                else if (a == 2) gp = V32h + (size_t)(h * 64 + row) * 2048 + kt * 32 + grp * 4;
                else             gp = V32l + (size_t)(h * 64 + row) * 2048 + kt * 32 + grp * 4;
                cpa16(sbase + (so + a * 64 * AST + row * AST + grp * 4) * 4, gp);
            }
    };

    issueKV(0); CP_COMMIT();          // G0: Q + KV0
    CP_WAIT0();
    __syncthreads();

    // Hoist Q fragments into registers
    const uint32_t bQh = sbase + (warp * 16) * AST * 4 + aro;
    const uint32_t bQl = bQh + 64 * AST * 4;
    uint32_t aqh[4][4], aql[4][4];
#pragma unroll
    for (int kk = 0; kk < 4; kk++) {
        ldsm4(aqh[kk][0], aqh[kk][1], aqh[kk][2], aqh[kk][3], bQh + kk * 32);
        ldsm4(aql[kk][0], aql[kk][1], aql[kk][2], aql[kk][3], bQl + kk * 32);
    }

    float o[8][4];
#pragma unroll
    for (int fn = 0; fn < 8; fn++)
#pragma unroll
        for (int r = 0; r < 4; r++) o[fn][r] = 0.f;
    float l0p = 0.f, l1p = 0.f;
    uint32_t pah[4][4], pal[4][4];    // P fragments of tile kt-1 (live across iters)

    const int rA = warp * 16 + g;
    const int row0g = q0 + rA, row1g = row0g + 8;

    for (int kt = 0; kt <= qi; kt++) {
        // KV(kt) is ready here (pre-loop wait for kt=0; end-of-iter wait after)
        const uint32_t stgC = sbase + (AQ_U + (kt & 1) * AKV_U) * 4;        // K of kt
        const uint32_t bKh = stgC + bro;
        const uint32_t bKl = bKh + 64 * AST * 4;
        const uint32_t stgP = sbase + (AQ_U + ((kt + 1) & 1) * AKV_U) * 4;  // V of kt-1
        const uint32_t bVh = stgP + 2 * 64 * AST * 4 + bro;
        const uint32_t bVl = bVh + 64 * AST * 4;
        const int k0 = kt * 64;

        // ---- S(kt) burst ----
        float s[8][4];
#pragma unroll
        for (int fn = 0; fn < 8; fn++)
#pragma unroll
            for (int r = 0; r < 4; r++) s[fn][r] = 0.f;
#pragma unroll
        for (int kk = 0; kk < 4; kk++) {
            const uint32_t ko = kk * 32;
#pragma unroll
            for (int fp = 0; fp < 4; fp++) {
                uint32_t kh0, kh1, kh2, kh3, kl0, kl1, kl2, kl3;
                ldsm4(kh0, kh1, kh2, kh3, bKh + fp * 16 * AST * 4 + ko);
                ldsm4(kl0, kl1, kl2, kl3, bKl + fp * 16 * AST * 4 + ko);
                mma16816(s[2*fp],   aqh[kk][0], aqh[kk][1], aqh[kk][2], aqh[kk][3], kh0, kh1);
                mma16816(s[2*fp+1], aqh[kk][0], aqh[kk][1], aqh[kk][2], aqh[kk][3], kh2, kh3);
                mma16816(s[2*fp],   aqh[kk][0], aqh[kk][1], aqh[kk][2], aqh[kk][3], kl0, kl1);
                mma16816(s[2*fp+1], aqh[kk][0], aqh[kk][1], aqh[kk][2], aqh[kk][3], kl2, kl3);
                mma16816(s[2*fp],   aql[kk][0], aql[kk][1], aql[kk][2], aql[kk][3], kh0, kh1);
                mma16816(s[2*fp+1], aql[kk][0], aql[kk][1], aql[kk][2], aql[kk][3], kh2, kh3);
            }
        }

        // ---- PV(kt-1) burst (independent of S(kt); fills tensor pipe) ----
        if (kt > 0) {
#pragma unroll
            for (int j = 0; j < 4; j++) {
#pragma unroll
                for (int fp = 0; fp < 4; fp++) {
                    uint32_t vh0, vh1, vh2, vh3, vl0, vl1, vl2, vl3;
                    ldsm4(vh0, vh1, vh2, vh3, bVh + fp * 16 * AST * 4 + j * 32);
                    ldsm4(vl0, vl1, vl2, vl3, bVl + fp * 16 * AST * 4 + j * 32);
                    mma16816(o[2*fp],   pah[j][0], pah[j][1], pah[j][2], pah[j][3], vh0, vh1);
                    mma16816(o[2*fp+1], pah[j][0], pah[j][1], pah[j][2], pah[j][3], vh2, vh3);
                    mma16816(o[2*fp],   pah[j][0], pah[j][1], pah[j][2], pah[j][3], vl0, vl1);
                    mma16816(o[2*fp+1], pah[j][0], pah[j][1], pah[j][2], pah[j][3], vl2, vl3);
                    mma16816(o[2*fp],   pal[j][0], pal[j][1], pal[j][2], pal[j][3], vh0, vh1);
                    mma16816(o[2*fp+1], pal[j][0], pal[j][1], pal[j][2], pal[j][3], vh2, vh3);
                }
            }
        }

        __syncthreads();              // all reads of stage (kt+1)&1 done
        if (kt + 1 <= qi) { issueKV(kt + 1); CP_COMMIT(); }

        // ---- softmax(kt) + pack (overlaps KV(kt+1) load) ----
        if (kt == qi) {
#pragma unroll
            for (int fn = 0; fn < 8; fn++) {
                int cg = k0 + fn * 8 + 2 * qd;
                if (cg > row0g)     s[fn][0] = -INFINITY;
                if (cg + 1 > row0g) s[fn][1] = -INFINITY;
                if (cg > row1g)     s[fn][2] = -INFINITY;
                if (cg + 1 > row1g) s[fn][3] = -INFINITY;
            }
        }
#pragma unroll
        for (int fn = 0; fn < 8; fn++) {
            s[fn][0] = __expf(s[fn][0]); s[fn][1] = __expf(s[fn][1]);
            s[fn][2] = __expf(s[fn][2]); s[fn][3] = __expf(s[fn][3]);
            l0p += s[fn][0] + s[fn][1];
            l1p += s[fn][2] + s[fn][3];
        }
#pragma unroll
        for (int j = 0; j < 4; j++) {
            bf162 h0 = pack2(s[2*j][0],   s[2*j][1]);
            bf162 h1 = pack2(s[2*j][2],   s[2*j][3]);
            bf162 h2 = pack2(s[2*j+1][0], s[2*j+1][1]);
            bf162 h3 = pack2(s[2*j+1][2], s[2*j+1][3]);
            bf162 e0 = pack2(s[2*j][0] - __bfloat162float(h0.x),   s[2*j][1] - __bfloat162float(h0.y));
            bf162 e1 = pack2(s[2*j][2] - __bfloat162float(h1.x),   s[2*j][3] - __bfloat162float(h1.y));
            bf162 e2 = pack2(s[2*j+1][0] - __bfloat162float(h2.x), s[2*j+1][1] - __bfloat162float(h2.y));
            bf162 e3 = pack2(s[2*j+1][2] - __bfloat162float(h3.x), s[2*j+1][3] - __bfloat162float(h3.y));
            pah[j][0] = *(uint32_t*)&h0; pah[j][1] = *(uint32_t*)&h1;
            pah[j][2] = *(uint32_t*)&h2; pah[j][3] = *(uint32_t*)&h3;
            pal[j][0] = *(uint32_t*)&e0; pal[j][1] = *(uint32_t*)&e1;
            pal[j][2] = *(uint32_t*)&e2; pal[j][3] = *(uint32_t*)&e3;
        }

        if (kt + 1 <= qi) {
            CP_WAIT0();               // KV(kt+1) landed (only group in flight)
            __syncthreads();
        }
    }

    // ---- final PV(qi) ----
    {
        const uint32_t stgP = sbase + (AQ_U + (qi & 1) * AKV_U) * 4;
        const uint32_t bVh = stgP + 2 * 64 * AST * 4 + bro;
        const uint32_t bVl = bVh + 64 * AST * 4;
#pragma unroll
        for (int j = 0; j < 4; j++) {
#pragma unroll
            for (int fp = 0; fp < 4; fp++) {
                uint32_t vh0, vh1, vh2, vh3, vl0, vl1, vl2, vl3;
                ldsm4(vh0, vh1, vh2, vh3, bVh + fp * 16 * AST * 4 + j * 32);
                ldsm4(vl0, vl1, vl2, vl3, bVl + fp * 16 * AST * 4 + j * 32);
                mma16816(o[2*fp],   pah[j][0], pah[j][1], pah[j][2], pah[j][3], vh0, vh1);
                mma16816(o[2*fp+1], pah[j][0], pah[j][1], pah[j][2], pah[j][3], vh2, vh3);
                mma16816(o[2*fp],   pah[j][0], pah[j][1], pah[j][2], pah[j][3], vl0, vl1);
                mma16816(o[2*fp+1], pah[j][0], pah[j][1], pah[j][2], pah[j][3], vl2, vl3);
                mma16816(o[2*fp],   pal[j][0], pal[j][1], pal[j][2], pal[j][3], vh0, vh1);
                mma16816(o[2*fp+1], pal[j][0], pal[j][1], pal[j][2], pal[j][3], vh2, vh3);
            }
        }
    }

    // l reduction across the 4 qd lanes of each row group
#pragma unroll
    for (int off = 1; off <= 2; off <<= 1) {
        l0p += __shfl_xor_sync(0xffffffffu, l0p, off);
        l1p += __shfl_xor_sync(0xffffffffu, l1p, off);
    }

    float i0 = 1.f / l0p, i1 = 1.f / l1p;
#pragma unroll
    for (int fn = 0; fn < 8; fn++) {
        int col = h * 64 + fn * 8 + 2 * qd;
        float v0 = o[fn][0] * i0, v1 = o[fn][1] * i0;
        float v2 = o[fn][2] * i1, v3 = o[fn][3] * i1;
        size_t p0 = (size_t)row0g * 512 + (col >> 1);
        size_t p1 = (size_t)row1g * 512 + (col >> 1);
        bf162 h0 = pack2(v0, v1), h1 = pack2(v2, v3);
        yh[p0] = h0; yh[p1] = h1;
        yl[p0] = pack2(v0 - __bfloat162float(h0.x), v1 - __bfloat162float(h0.y));
        yl[p1] = pack2(v2 - __bfloat162float(h1.x), v3 - __bfloat162float(h1.y));
    }
}

// ---------------------------------------------------------------------------
extern "C" void kernel_launch(void* const* d_in, const int* in_sizes, int n_in,
                              void* d_out, int out_size) {
    const float* x     = (const float*)d_in[0];
    const float* Wqkv  = (const float*)d_in[1];
    const float* bqkv  = (const float*)d_in[2];
    const float* Wproj = (const float*)d_in[3];
    const float* bproj = (const float*)d_in[4];
    float* out = (float*)d_out;

    bf162 *xh, *xl, *wqh, *wql, *wph, *wpl, *qh, *ql, *vth, *vtl, *yh, *yl;
    cudaGetSymbolAddress((void**)&xh, g_xh);   cudaGetSymbolAddress((void**)&xl, g_xl);
    cudaGetSymbolAddress((void**)&wqh, g_wqh); cudaGetSymbolAddress((void**)&wql, g_wql);
    cudaGetSymbolAddress((void**)&wph, g_wph); cudaGetSymbolAddress((void**)&wpl, g_wpl);
    cudaGetSymbolAddress((void**)&qh, g_qh);   cudaGetSymbolAddress((void**)&ql, g_ql);
    cudaGetSymbolAddress((void**)&vth, g_vth); cudaGetSymbolAddress((void**)&vtl, g_vtl);
    cudaGetSymbolAddress((void**)&yh, g_yh);   cudaGetSymbolAddress((void**)&yl, g_yl);

    cudaFuncSetAttribute(gemm_bf16x3, cudaFuncAttributeMaxDynamicSharedMemorySize, GSMEM);
    cudaFuncSetAttribute(attn_mma, cudaFuncAttributeMaxDynamicSharedMemorySize, ATTN_SMEM);

    split3_kernel<<<(NPX + NPQ + NPP + 255) / 256, 256>>>(
        x, Wqkv, Wproj, xh, xl, wqh, wql, wph, wpl);

    // QKV projection: Q cols scaled 1/8, V cols (>=2048) written transposed
    gemm_bf16x3<<<dim3(24, 32), 256, GSMEM>>>(xh, xl, wqh, wql, bqkv,
                                              nullptr, qh, ql, vth, vtl,
                                              T_SEQ, 3072, 512, 1024, 2048);
    attn_mma<<<dim3(64, 16), 128, ATTN_SMEM>>>(qh, ql, vth, vtl, yh, yl);
    gemm_bf16x3<<<dim3(8, 32), 256, GSMEM>>>(yh, yl, wph, wpl, bproj,
                                             out, nullptr, nullptr, nullptr, nullptr,
                                             T_SEQ, 1024, 512, 0, 1 << 30);
}

// round 17
// speedup vs baseline: 1.6517x; 1.5606x over previous
#include <cuda_runtime.h>
#include <cuda_bf16.h>
#include <stdint.h>
#include <math.h>

typedef __nv_bfloat16  bf16;
typedef __nv_bfloat162 bf162;

#define T_SEQ 4096

// Scratch (device globals; no allocation allowed)
__device__ __align__(16) bf162 g_xh[T_SEQ * 512],  g_xl[T_SEQ * 512];
__device__ __align__(16) bf162 g_wqh[3072 * 512],  g_wql[3072 * 512];
__device__ __align__(16) bf162 g_wph[1024 * 512],  g_wpl[1024 * 512];
__device__ __align__(16) bf162 g_qh[T_SEQ * 1536], g_ql[T_SEQ * 1536];
__device__ __align__(16) bf162 g_vth[16 * 64 * 2048], g_vtl[16 * 64 * 2048];
__device__ __align__(16) bf162 g_yh[T_SEQ * 512],  g_yl[T_SEQ * 512];

// single-instruction bf16x2 pack: .x = a (lo half), .y = b (hi half)
__device__ __forceinline__ bf162 pack2(float a, float b) {
    uint32_t r;
    asm("cvt.rn.bf16x2.f32 %0, %1, %2;" : "=r"(r) : "f"(b), "f"(a));
    return *(bf162*)&r;
}

__device__ __forceinline__ void cpa16(uint32_t dst, const void* src) {
    asm volatile("cp.async.cg.shared.global [%0], [%1], 16;" :: "r"(dst), "l"(src));
}
#define CP_COMMIT() asm volatile("cp.async.commit_group;")
#define CP_WAIT1()  asm volatile("cp.async.wait_group 1;")
#define CP_WAIT0()  asm volatile("cp.async.wait_group 0;")

__device__ __forceinline__ uint32_t smem_u32(const void* p) {
    uint32_t a;
    asm("{ .reg .u64 tmp; cvta.to.shared.u64 tmp, %1; cvt.u32.u64 %0, tmp; }"
        : "=r"(a) : "l"(p));
    return a;
}

// ldmatrix x4: r0..r3 <- four 8x8 b16 matrices, per-lane row addresses
__device__ __forceinline__ void ldsm4(uint32_t& r0, uint32_t& r1,
                                      uint32_t& r2, uint32_t& r3, uint32_t a) {
    asm volatile("ldmatrix.sync.aligned.m8n8.x4.shared.b16 {%0,%1,%2,%3}, [%4];"
                 : "=r"(r0), "=r"(r1), "=r"(r2), "=r"(r3) : "r"(a));
}

// Fused fp32 -> (bf16 hi, bf16 lo) split for x, W_qkv, W_proj (one launch)
#define NPX (T_SEQ * 512)
#define NPQ (3072 * 512)
#define NPP (1024 * 512)
__global__ void split3_kernel(const float* __restrict__ x,
                              const float* __restrict__ wq,
                              const float* __restrict__ wp,
                              bf162* __restrict__ xh, bf162* __restrict__ xl,
                              bf162* __restrict__ wqh, bf162* __restrict__ wql,
                              bf162* __restrict__ wph, bf162* __restrict__ wpl) {
    int i = blockIdx.x * 256 + threadIdx.x;
    const float* in; bf162 *ho, *lo;
    if (i < NPX)            { in = x;  ho = xh;  lo = xl; }
    else if (i < NPX + NPQ) { i -= NPX; in = wq; ho = wqh; lo = wql; }
    else                    { i -= NPX + NPQ; in = wp; ho = wph; lo = wpl; }
    float2 v = ((const float2*)in)[i];
    bf162 h = pack2(v.x, v.y);
    ho[i] = h;
    lo[i] = pack2(v.x - __bfloat162float(h.x), v.y - __bfloat162float(h.y));
}

__device__ __forceinline__ void mma16816(float* d, uint32_t a0, uint32_t a1,
                                         uint32_t a2, uint32_t a3,
                                         uint32_t b0, uint32_t b1) {
    asm volatile("mma.sync.aligned.m16n8k16.row.col.f32.bf16.bf16.f32 "
                 "{%0,%1,%2,%3}, {%4,%5,%6,%7}, {%8,%9}, {%0,%1,%2,%3};\n"
                 : "+f"(d[0]), "+f"(d[1]), "+f"(d[2]), "+f"(d[3])
                 : "r"(a0), "r"(a1), "r"(a2), "r"(a3), "r"(b0), "r"(b1));
}

// ---------------------------------------------------------------------------
// GEMM bf16x3, 2-stage cp.async pipeline, ldmatrix, 2 blocks/SM.
// Term-major MMA sweeps (16 indep accumulators per sweep).
// C[M,N] = (Ah+Al)(Bh+Bl)^T + bias.  Kp = K/2 pairs, BK=32.
// Cols < scale_cols: *0.125 (exact pow2).  Cols >= v_cols: written TRANSPOSED
// into Vth/Vtl as vt[col - v_cols][token-pair] (fuses the V transpose).
// ---------------------------------------------------------------------------
#define GST 20
#define GSTAGE_U (4 * 128 * GST)
#define GSMEM (2 * GSTAGE_U * 4)

__global__ __launch_bounds__(256, 2)
void gemm_bf16x3(const bf162* __restrict__ Ah_, const bf162* __restrict__ Al_,
                 const bf162* __restrict__ Bh_, const bf162* __restrict__ Bl_,
                 const float* __restrict__ bias, float* __restrict__ Cf,
                 bf162* __restrict__ Ch, bf162* __restrict__ Cl,
                 bf162* __restrict__ Vth, bf162* __restrict__ Vtl,
                 int M, int N, int Kp, int scale_cols, int v_cols) {
    extern __shared__ uint32_t dsm[];
    const int t = threadIdx.x, lane = t & 31, warp = t >> 5;
    const int g = lane >> 2, qd = lane & 3;
    const int wm = warp & 1, wn = warp >> 1;
    const int m0 = blockIdx.y * 128, n0 = blockIdx.x * 128;
    const uint32_t* src[4] = {(const uint32_t*)Ah_, (const uint32_t*)Al_,
                              (const uint32_t*)Bh_, (const uint32_t*)Bl_};
    const uint32_t sbase = smem_u32(dsm);
    const int nk = Kp >> 4;

    const int lr = lane & 7;
    const uint32_t aro = ((((lane >> 3) & 1) * 8 + lr) * GST + (lane >> 4) * 4) * 4;
    const uint32_t bro = (((lane >> 4) * 8 + lr) * GST + ((lane >> 3) & 1) * 4) * 4;

    float acc[4][4][4];
#pragma unroll
    for (int a = 0; a < 4; a++)
#pragma unroll
        for (int b = 0; b < 4; b++)
#pragma unroll
            for (int r = 0; r < 4; r++) acc[a][b][r] = 0.f;

    auto issue = [&](int k) {
        uint32_t so = (uint32_t)(k & 1) * GSTAGE_U;
        int kp0 = k << 4;
#pragma unroll
        for (int a = 0; a < 4; a++) {
            int rbase = (a < 2) ? m0 : n0;
#pragma unroll
            for (int hf = 0; hf < 2; hf++) {
                int w = hf * 256 + t, row = w >> 2, grp = w & 3;
                const uint32_t* gp = src[a] + (size_t)(rbase + row) * Kp + kp0 + grp * 4;
                cpa16(sbase + (so + a * 128 * GST + row * GST + grp * 4) * 4, gp);
            }
        }
        CP_COMMIT();
    };

    issue(0);
    issue(1);
    for (int k = 0; k < nk; k++) {
        CP_WAIT1();
        __syncthreads();

        const uint32_t stg = sbase + (uint32_t)(k & 1) * GSTAGE_U * 4;
        const uint32_t bAh = stg + (wm * 64) * GST * 4 + aro;
        const uint32_t bAl = bAh + 128 * GST * 4;
        const uint32_t bBh = stg + 2 * 128 * GST * 4 + (wn * 32) * GST * 4 + bro;
        const uint32_t bBl = bBh + 128 * GST * 4;
#pragma unroll
        for (int kk = 0; kk < 2; kk++) {
            const uint32_t ko = kk * 32;
            uint32_t ah[4][4], al[4][4], bh[2][4], bl[2][4];
#pragma unroll
            for (int fm = 0; fm < 4; fm++) {
                ldsm4(ah[fm][0], ah[fm][1], ah[fm][2], ah[fm][3],
                      bAh + fm * 16 * GST * 4 + ko);
                ldsm4(al[fm][0], al[fm][1], al[fm][2], al[fm][3],
                      bAl + fm * 16 * GST * 4 + ko);
            }
#pragma unroll
            for (int fp = 0; fp < 2; fp++) {
                ldsm4(bh[fp][0], bh[fp][1], bh[fp][2], bh[fp][3],
                      bBh + fp * 16 * GST * 4 + ko);
                ldsm4(bl[fp][0], bl[fp][1], bl[fp][2], bl[fp][3],
                      bBl + fp * 16 * GST * 4 + ko);
            }
            // term-major sweeps: all hh, then hl, then lh (16 indep accs each)
#pragma unroll
            for (int fp = 0; fp < 2; fp++)
#pragma unroll
                for (int hf = 0; hf < 2; hf++)
#pragma unroll
                    for (int fm = 0; fm < 4; fm++)
                        mma16816(acc[fm][2*fp+hf], ah[fm][0], ah[fm][1], ah[fm][2], ah[fm][3],
                                 bh[fp][2*hf], bh[fp][2*hf+1]);
#pragma unroll
            for (int fp = 0; fp < 2; fp++)
#pragma unroll
                for (int hf = 0; hf < 2; hf++)
#pragma unroll
                    for (int fm = 0; fm < 4; fm++)
                        mma16816(acc[fm][2*fp+hf], ah[fm][0], ah[fm][1], ah[fm][2], ah[fm][3],
                                 bl[fp][2*hf], bl[fp][2*hf+1]);
#pragma unroll
            for (int fp = 0; fp < 2; fp++)
#pragma unroll
                for (int hf = 0; hf < 2; hf++)
#pragma unroll
                    for (int fm = 0; fm < 4; fm++)
                        mma16816(acc[fm][2*fp+hf], al[fm][0], al[fm][1], al[fm][2], al[fm][3],
                                 bh[fp][2*hf], bh[fp][2*hf+1]);
        }
        __syncthreads();
        if (k + 2 < nk) issue(k + 2); else CP_COMMIT();
    }

    const float sc = (n0 < scale_cols) ? 0.125f : 1.0f;   // tile-uniform
    const bool vtile = (n0 >= v_cols);                     // tile-uniform
#pragma unroll
    for (int fm = 0; fm < 4; fm++)
#pragma unroll
        for (int fn = 0; fn < 4; fn++) {
            int row = m0 + wm * 64 + fm * 16 + g;
            int col = n0 + wn * 32 + fn * 8 + 2 * qd;
            float b0 = bias[col], b1 = bias[col + 1];
            float v0 = (acc[fm][fn][0] + b0) * sc, v1 = (acc[fm][fn][1] + b1) * sc;
            float v2 = (acc[fm][fn][2] + b0) * sc, v3 = (acc[fm][fn][3] + b1) * sc;
            if (Cf) {
                float2 p0 = {v0, v1}, p1 = {v2, v3};
                *(float2*)&Cf[(size_t)row * N + col] = p0;
                *(float2*)&Cf[(size_t)(row + 8) * N + col] = p1;
            } else if (!vtile) {
                size_t c0 = (size_t)row * (N >> 1) + (col >> 1);
                size_t c1 = (size_t)(row + 8) * (N >> 1) + (col >> 1);
                bf162 h0 = pack2(v0, v1), h1 = pack2(v2, v3);
                Ch[c0] = h0; Ch[c1] = h1;
                Cl[c0] = pack2(v0 - __bfloat162float(h0.x), v1 - __bfloat162float(h0.y));
                Cl[c1] = pack2(v2 - __bfloat162float(h1.x), v3 - __bfloat162float(h1.y));
            } else {
                // transposed V store: vt[(col - v_cols)][token-pair]
                float e0 = __shfl_xor_sync(0xffffffffu, v0, 4);
                float e1 = __shfl_xor_sync(0xffffffffu, v1, 4);
                float e2 = __shfl_xor_sync(0xffffffffu, v2, 4);
                float e3 = __shfl_xor_sync(0xffffffffu, v3, 4);
                int colV = col - v_cols;
                if ((g & 1) == 0) {
                    size_t base = (size_t)colV * 2048 + (row >> 1);
                    bf162 h0 = pack2(v0, e0), h1 = pack2(v2, e2);
                    Vth[base] = h0; Vth[base + 4] = h1;
                    Vtl[base]     = pack2(v0 - __bfloat162float(h0.x), e0 - __bfloat162float(h0.y));
                    Vtl[base + 4] = pack2(v2 - __bfloat162float(h1.x), e2 - __bfloat162float(h1.y));
                } else {
                    size_t base = (size_t)(colV + 1) * 2048 + ((row - 1) >> 1);
                    bf162 h0 = pack2(e1, v1), h1 = pack2(e3, v3);
                    Vth[base] = h0; Vth[base + 4] = h1;
                    Vtl[base]     = pack2(e1 - __bfloat162float(h0.x), v1 - __bfloat162float(h0.y));
                    Vtl[base + 4] = pack2(e3 - __bfloat162float(h1.x), v3 - __bfloat162float(h1.y));
                }
            }
        }
}

// ---------------------------------------------------------------------------
// Flash attention (causal), bf16x3 mma, ldmatrix, q-tile 64 rows, 4 warps,
// 2-stage cp.async K/V pipeline, 2 blocks/SM.
// PV deferred one tile: each iter fronts S(kt)+PV(kt-1) as one independent
// MMA burst; softmax(kt) overlaps the KV(kt+1) load; wait_group 0 at the
// consume point (issue distance is 1 with a 2-stage buffer).
// ---------------------------------------------------------------------------
#define AST 36
#define AQ_U   (2 * 64 * AST)    // Q hi + lo (64 rows)
#define AKV_U  (4 * 64 * AST)    // per stage: Kh, Kl, Vh, Vl
#define ATTN_SMEM ((AQ_U + 2 * AKV_U) * 4)

__global__ __launch_bounds__(128, 2)
void attn_mma(const bf162* __restrict__ qh, const bf162* __restrict__ ql,
              const bf162* __restrict__ vth, const bf162* __restrict__ vtl,
              bf162* __restrict__ yh, bf162* __restrict__ yl) {
    extern __shared__ uint32_t dsm[];
    const int t = threadIdx.x, lane = t & 31, warp = t >> 5;
    const int g = lane >> 2, qd = lane & 3;
    const int h = blockIdx.y, qi = 63 - blockIdx.x, q0 = qi * 64;
    const uint32_t sbase = smem_u32(dsm);
    const uint32_t* Q32h = (const uint32_t*)qh;
    const uint32_t* Q32l = (const uint32_t*)ql;
    const uint32_t* V32h = (const uint32_t*)vth;
    const uint32_t* V32l = (const uint32_t*)vtl;

    const int lr = lane & 7;
    const uint32_t aro = ((((lane >> 3) & 1) * 8 + lr) * AST + (lane >> 4) * 4) * 4;
    const uint32_t bro = (((lane >> 4) * 8 + lr) * AST + ((lane >> 3) & 1) * 4) * 4;

    // stage Q (64 rows x 32 pairs, hi+lo)
#pragma unroll
    for (int a = 0; a < 2; a++)
#pragma unroll
        for (int hf = 0; hf < 4; hf++) {
            int w = hf * 128 + t, row = w >> 3, grp = w & 7;
            const uint32_t* gp = (a ? Q32l : Q32h) + (size_t)(q0 + row) * 1536 + h * 32 + grp * 4;
            cpa16(sbase + (a * 64 * AST + row * AST + grp * 4) * 4, gp);
        }

    auto issueKV = [&](int kt) {
        uint32_t so = AQ_U + (uint32_t)(kt & 1) * AKV_U;
        int k0 = kt * 64;
#pragma unroll
        for (int a = 0; a < 4; a++)
#pragma unroll
            for (int hf = 0; hf < 4; hf++) {
                int w = hf * 128 + t, row = w >> 3, grp = w & 7;
                const uint32_t* gp;
                if (a == 0)      gp = Q32h + (size_t)(k0 + row) * 1536 + 512 + h * 32 + grp * 4;
                else if (a == 1) gp = Q32l + (size_t)(k0 + row) * 1536 + 512 + h * 32 + grp * 4;
                else if (a == 2) gp = V32h + (size_t)(h * 64 + row) * 2048 + kt * 32 + grp * 4;
                else             gp = V32l + (size_t)(h * 64 + row) * 2048 + kt * 32 + grp * 4;
                cpa16(sbase + (so + a * 64 * AST + row * AST + grp * 4) * 4, gp);
            }
    };

    issueKV(0); CP_COMMIT();          // G0: Q + KV0
    CP_WAIT0();
    __syncthreads();

    // Hoist Q fragments into registers
    const uint32_t bQh = sbase + (warp * 16) * AST * 4 + aro;
    const uint32_t bQl = bQh + 64 * AST * 4;
    uint32_t aqh[4][4], aql[4][4];
#pragma unroll
    for (int kk = 0; kk < 4; kk++) {
        ldsm4(aqh[kk][0], aqh[kk][1], aqh[kk][2], aqh[kk][3], bQh + kk * 32);
        ldsm4(aql[kk][0], aql[kk][1], aql[kk][2], aql[kk][3], bQl + kk * 32);
    }

    float o[8][4];
#pragma unroll
    for (int fn = 0; fn < 8; fn++)
#pragma unroll
        for (int r = 0; r < 4; r++) o[fn][r] = 0.f;
    float l0p = 0.f, l1p = 0.f;
    uint32_t pah[4][4], pal[4][4];    // P fragments of tile kt-1 (live across iters)

    const int rA = warp * 16 + g;
    const int row0g = q0 + rA, row1g = row0g + 8;

    for (int kt = 0; kt <= qi; kt++) {
        // KV(kt) is ready here (pre-loop wait for kt=0; end-of-iter wait after)
        const uint32_t stgC = sbase + (AQ_U + (kt & 1) * AKV_U) * 4;        // K of kt
        const uint32_t bKh = stgC + bro;
        const uint32_t bKl = bKh + 64 * AST * 4;
        const uint32_t stgP = sbase + (AQ_U + ((kt + 1) & 1) * AKV_U) * 4;  // V of kt-1
        const uint32_t bVh = stgP + 2 * 64 * AST * 4 + bro;
        const uint32_t bVl = bVh + 64 * AST * 4;
        const int k0 = kt * 64;

        // ---- S(kt) burst ----
        float s[8][4];
#pragma unroll
        for (int fn = 0; fn < 8; fn++)
#pragma unroll
            for (int r = 0; r < 4; r++) s[fn][r] = 0.f;
#pragma unroll
        for (int kk = 0; kk < 4; kk++) {
            const uint32_t ko = kk * 32;
#pragma unroll
            for (int fp = 0; fp < 4; fp++) {
                uint32_t kh0, kh1, kh2, kh3, kl0, kl1, kl2, kl3;
                ldsm4(kh0, kh1, kh2, kh3, bKh + fp * 16 * AST * 4 + ko);
                ldsm4(kl0, kl1, kl2, kl3, bKl + fp * 16 * AST * 4 + ko);
                mma16816(s[2*fp],   aqh[kk][0], aqh[kk][1], aqh[kk][2], aqh[kk][3], kh0, kh1);
                mma16816(s[2*fp+1], aqh[kk][0], aqh[kk][1], aqh[kk][2], aqh[kk][3], kh2, kh3);
                mma16816(s[2*fp],   aqh[kk][0], aqh[kk][1], aqh[kk][2], aqh[kk][3], kl0, kl1);
                mma16816(s[2*fp+1], aqh[kk][0], aqh[kk][1], aqh[kk][2], aqh[kk][3], kl2, kl3);
                mma16816(s[2*fp],   aql[kk][0], aql[kk][1], aql[kk][2], aql[kk][3], kh0, kh1);
                mma16816(s[2*fp+1], aql[kk][0], aql[kk][1], aql[kk][2], aql[kk][3], kh2, kh3);
            }
        }

        // ---- PV(kt-1) burst (independent of S(kt); fills tensor pipe) ----
        if (kt > 0) {
#pragma unroll
            for (int j = 0; j < 4; j++) {
#pragma unroll
                for (int fp = 0; fp < 4; fp++) {
                    uint32_t vh0, vh1, vh2, vh3, vl0, vl1, vl2, vl3;
                    ldsm4(vh0, vh1, vh2, vh3, bVh + fp * 16 * AST * 4 + j * 32);
                    ldsm4(vl0, vl1, vl2, vl3, bVl + fp * 16 * AST * 4 + j * 32);
                    mma16816(o[2*fp],   pah[j][0], pah[j][1], pah[j][2], pah[j][3], vh0, vh1);
                    mma16816(o[2*fp+1], pah[j][0], pah[j][1], pah[j][2], pah[j][3], vh2, vh3);
                    mma16816(o[2*fp],   pah[j][0], pah[j][1], pah[j][2], pah[j][3], vl0, vl1);
                    mma16816(o[2*fp+1], pah[j][0], pah[j][1], pah[j][2], pah[j][3], vl2, vl3);
                    mma16816(o[2*fp],   pal[j][0], pal[j][1], pal[j][2], pal[j][3], vh0, vh1);
                    mma16816(o[2*fp+1], pal[j][0], pal[j][1], pal[j][2], pal[j][3], vh2, vh3);
                }
            }
        }

        __syncthreads();              // all reads of stage (kt+1)&1 done
        if (kt + 1 <= qi) { issueKV(kt + 1); CP_COMMIT(); }

        // ---- softmax(kt) + pack (overlaps KV(kt+1) load) ----
        if (kt == qi) {
#pragma unroll
            for (int fn = 0; fn < 8; fn++) {
                int cg = k0 + fn * 8 + 2 * qd;
                if (cg > row0g)     s[fn][0] = -INFINITY;
                if (cg + 1 > row0g) s[fn][1] = -INFINITY;
                if (cg > row1g)     s[fn][2] = -INFINITY;
                if (cg + 1 > row1g) s[fn][3] = -INFINITY;
            }
        }
#pragma unroll
        for (int fn = 0; fn < 8; fn++) {
            s[fn][0] = __expf(s[fn][0]); s[fn][1] = __expf(s[fn][1]);
            s[fn][2] = __expf(s[fn][2]); s[fn][3] = __expf(s[fn][3]);
            l0p += s[fn][0] + s[fn][1];
            l1p += s[fn][2] + s[fn][3];
        }
#pragma unroll
        for (int j = 0; j < 4; j++) {
            bf162 h0 = pack2(s[2*j][0],   s[2*j][1]);
            bf162 h1 = pack2(s[2*j][2],   s[2*j][3]);
            bf162 h2 = pack2(s[2*j+1][0], s[2*j+1][1]);
            bf162 h3 = pack2(s[2*j+1][2], s[2*j+1][3]);
            bf162 e0 = pack2(s[2*j][0] - __bfloat162float(h0.x),   s[2*j][1] - __bfloat162float(h0.y));
            bf162 e1 = pack2(s[2*j][2] - __bfloat162float(h1.x),   s[2*j][3] - __bfloat162float(h1.y));
            bf162 e2 = pack2(s[2*j+1][0] - __bfloat162float(h2.x), s[2*j+1][1] - __bfloat162float(h2.y));
            bf162 e3 = pack2(s[2*j+1][2] - __bfloat162float(h3.x), s[2*j+1][3] - __bfloat162float(h3.y));
            pah[j][0] = *(uint32_t*)&h0; pah[j][1] = *(uint32_t*)&h1;
            pah[j][2] = *(uint32_t*)&h2; pah[j][3] = *(uint32_t*)&h3;
            pal[j][0] = *(uint32_t*)&e0; pal[j][1] = *(uint32_t*)&e1;
            pal[j][2] = *(uint32_t*)&e2; pal[j][3] = *(uint32_t*)&e3;
        }

        if (kt + 1 <= qi) {
            CP_WAIT0();               // KV(kt+1) landed (only group in flight)
            __syncthreads();
        }
    }

    // ---- final PV(qi) ----
    {
        const uint32_t stgP = sbase + (AQ_U + (qi & 1) * AKV_U) * 4;
        const uint32_t bVh = stgP + 2 * 64 * AST * 4 + bro;
        const uint32_t bVl = bVh + 64 * AST * 4;
#pragma unroll
        for (int j = 0; j < 4; j++) {
#pragma unroll
            for (int fp = 0; fp < 4; fp++) {
                uint32_t vh0, vh1, vh2, vh3, vl0, vl1, vl2, vl3;
                ldsm4(vh0, vh1, vh2, vh3, bVh + fp * 16 * AST * 4 + j * 32);
                ldsm4(vl0, vl1, vl2, vl3, bVl + fp * 16 * AST * 4 + j * 32);
                mma16816(o[2*fp],   pah[j][0], pah[j][1], pah[j][2], pah[j][3], vh0, vh1);
                mma16816(o[2*fp+1], pah[j][0], pah[j][1], pah[j][2], pah[j][3], vh2, vh3);
                mma16816(o[2*fp],   pah[j][0], pah[j][1], pah[j][2], pah[j][3], vl0, vl1);
                mma16816(o[2*fp+1], pah[j][0], pah[j][1], pah[j][2], pah[j][3], vl2, vl3);
                mma16816(o[2*fp],   pal[j][0], pal[j][1], pal[j][2], pal[j][3], vh0, vh1);
                mma16816(o[2*fp+1], pal[j][0], pal[j][1], pal[j][2], pal[j][3], vh2, vh3);
            }
        }
    }

    // l reduction across the 4 qd lanes of each row group
#pragma unroll
    for (int off = 1; off <= 2; off <<= 1) {
        l0p += __shfl_xor_sync(0xffffffffu, l0p, off);
        l1p += __shfl_xor_sync(0xffffffffu, l1p, off);
    }

    float i0 = 1.f / l0p, i1 = 1.f / l1p;
#pragma unroll
    for (int fn = 0; fn < 8; fn++) {
        int col = h * 64 + fn * 8 + 2 * qd;
        float v0 = o[fn][0] * i0, v1 = o[fn][1] * i0;
        float v2 = o[fn][2] * i1, v3 = o[fn][3] * i1;
        size_t p0 = (size_t)row0g * 512 + (col >> 1);
        size_t p1 = (size_t)row1g * 512 + (col >> 1);
        bf162 h0 = pack2(v0, v1), h1 = pack2(v2, v3);
        yh[p0] = h0; yh[p1] = h1;
        yl[p0] = pack2(v0 - __bfloat162float(h0.x), v1 - __bfloat162float(h0.y));
        yl[p1] = pack2(v2 - __bfloat162float(h1.x), v3 - __bfloat162float(h1.y));
    }
}

// ---------------------------------------------------------------------------
extern "C" void kernel_launch(void* const* d_in, const int* in_sizes, int n_in,
                              void* d_out, int out_size) {
    const float* x     = (const float*)d_in[0];
    const float* Wqkv  = (const float*)d_in[1];
    const float* bqkv  = (const float*)d_in[2];
    const float* Wproj = (const float*)d_in[3];
    const float* bproj = (const float*)d_in[4];
    float* out = (float*)d_out;

    bf162 *xh, *xl, *wqh, *wql, *wph, *wpl, *qh, *ql, *vth, *vtl, *yh, *yl;
    cudaGetSymbolAddress((void**)&xh, g_xh);   cudaGetSymbolAddress((void**)&xl, g_xl);
    cudaGetSymbolAddress((void**)&wqh, g_wqh); cudaGetSymbolAddress((void**)&wql, g_wql);
    cudaGetSymbolAddress((void**)&wph, g_wph); cudaGetSymbolAddress((void**)&wpl, g_wpl);
    cudaGetSymbolAddress((void**)&qh, g_qh);   cudaGetSymbolAddress((void**)&ql, g_ql);
    cudaGetSymbolAddress((void**)&vth, g_vth); cudaGetSymbolAddress((void**)&vtl, g_vtl);
    cudaGetSymbolAddress((void**)&yh, g_yh);   cudaGetSymbolAddress((void**)&yl, g_yl);

    cudaFuncSetAttribute(gemm_bf16x3, cudaFuncAttributeMaxDynamicSharedMemorySize, GSMEM);
    cudaFuncSetAttribute(attn_mma, cudaFuncAttributeMaxDynamicSharedMemorySize, ATTN_SMEM);

    split3_kernel<<<(NPX + NPQ + NPP + 255) / 256, 256>>>(
        x, Wqkv, Wproj, xh, xl, wqh, wql, wph, wpl);

    // QKV projection: Q cols scaled 1/8, V cols (>=2048) written transposed
    gemm_bf16x3<<<dim3(24, 32), 256, GSMEM>>>(xh, xl, wqh, wql, bqkv,
                                              nullptr, qh, ql, vth, vtl,
                                              T_SEQ, 3072, 512, 1024, 2048);
    attn_mma<<<dim3(64, 16), 128, ATTN_SMEM>>>(qh, ql, vth, vtl, yh, yl);
    gemm_bf16x3<<<dim3(8, 32), 256, GSMEM>>>(yh, yl, wph, wpl, bproj,
                                             out, nullptr, nullptr, nullptr, nullptr,
                                             T_SEQ, 1024, 512, 0, 1 << 30);
}